// round 17
// baseline (speedup 1.0000x reference)
#include <cuda_runtime.h>
#include <cuda_fp16.h>
#include <cstdint>

#define B_  2
#define N_  512
#define C_  128
#define H_  8
#define STRIDE_I 18                // CTAs per stripe; grid = 16*18 = 288

// ---------------- scratch (device globals) ----------------------------------
__device__ float g_Q[B_ * N_ * C_];               // pre-scaled by 0.25
__device__ float g_K[B_ * N_ * C_];
__device__ float g_V[B_ * N_ * C_];
__device__ float g_S[B_ * H_ * N_ * N_];          // [b,h,i,j]; holds exp(clamp(s))
__device__ float g_cs2[STRIDE_I * 16 * N_];       // colsum partials [w0][bh][j]
__device__ __half g_W0T[C_ * C_];                 // WeT fp16 [d][c]

// ---------------- helpers ----------------------------------------------------
__device__ __forceinline__ uint32_t smem_u32(const void* p) {
    uint32_t a;
    asm("{ .reg .u64 t; cvta.to.shared.u64 t, %1; cvt.u32.u64 %0, t; }" : "=r"(a) : "l"(p));
    return a;
}
#define LDSM_X4(r0, r1, r2, r3, a) \
    asm volatile("ldmatrix.sync.aligned.m8n8.x4.shared.b16 {%0,%1,%2,%3}, [%4];" \
                 : "=r"(r0), "=r"(r1), "=r"(r2), "=r"(r3) : "r"(a))
#define MMA16816(c, a0, a1, a2, a3, b0, b1) \
    asm volatile("mma.sync.aligned.m16n8k16.row.col.f32.f16.f16.f32 " \
                 "{%0,%1,%2,%3}, {%4,%5,%6,%7}, {%8,%9}, {%0,%1,%2,%3};" \
                 : "+f"((c)[0]), "+f"((c)[1]), "+f"((c)[2]), "+f"((c)[3]) \
                 : "r"(a0), "r"(a1), "r"(a2), "r"(a3), "r"(b0), "r"(b1))
#define STS64(a, u0, u1) \
    asm volatile("st.shared.v2.u32 [%0], {%1, %2};" :: "r"(a), "r"(u0), "r"(u1) : "memory")
#define LDS128F(v, a) \
    asm volatile("ld.shared.v4.f32 {%0,%1,%2,%3}, [%4];" \
                 : "=f"((v).x), "=f"((v).y), "=f"((v).z), "=f"((v).w) : "r"(a))
#define LDS64F(v, a) \
    asm volatile("ld.shared.v2.f32 {%0,%1}, [%2];" : "=f"((v).x), "=f"((v).y) : "r"(a))
#define CP_ASYNC16(s, g) \
    asm volatile("cp.async.cg.shared.global [%0], [%1], 16;" :: "r"(s), "l"(g) : "memory")
#define CP_COMMIT()  asm volatile("cp.async.commit_group;" ::: "memory")
#define CP_WAIT0()   asm volatile("cp.async.wait_group 0;" ::: "memory")

// XOR swizzle on 16B chunks within a 256B row (bits 4..6)
__device__ __forceinline__ uint32_t swz(int row, uint32_t cb) {
    return (uint32_t)row * 256u + (cb ^ (((uint32_t)row & 7u) << 4));
}

// dynamic smem byte offsets
#define SM_E16A 0u                 // 64x128 fp16 swizzled (16 KB)
#define SM_E16B 16384u             // second fp16 buffer (16 KB)
#define SM_E32  32768u             // fp32 e staging / initial W staging (32 KB)
#define SM_K    65536u             // 64 rows x 132 floats padded (33792 B)
#define SM_TOT  99328u             // ~97 KB -> 2 CTAs/SM

// ============================================================================
// Kernel 0: transpose + fp16 We -> g_W0T [d][c]
// ============================================================================
__global__ void prep_w_kernel(const float* __restrict__ We) {
    int idx = blockIdx.x * 256 + threadIdx.x;      // [0, 16384)
    int d = idx >> 7, c = idx & 127;
    g_W0T[idx] = __float2half_rn(__ldg(We + c * C_ + d));
}

// ============================================================================
// Kernel 1a: Q/K projections (Q pre-scaled by 0.25). 65536 threads.
// ============================================================================
__global__ void qk_kernel(const float* __restrict__ h, const float* __restrict__ Wq,
                          const float* __restrict__ Wk) {
    int gid = blockIdx.x * blockDim.x + threadIdx.x;   // [0, 65536)
    int row = gid >> 6, q = gid & 63;
    int mat = q >> 5, d = (q & 31) * 4;
    const float* W   = mat ? Wk : Wq;
    float*       out = mat ? g_K : g_Q;
    const float* hrow = h + (size_t)row * C_;
    float4 acc = make_float4(0.f, 0.f, 0.f, 0.f);
#pragma unroll 4
    for (int c = 0; c < C_; c++) {
        float  hv = __ldg(hrow + c);
        float4 w  = *(const float4*)(W + (size_t)c * C_ + d);
        acc.x += hv * w.x; acc.y += hv * w.y; acc.z += hv * w.z; acc.w += hv * w.w;
    }
    if (mat == 0) { acc.x *= .25f; acc.y *= .25f; acc.z *= .25f; acc.w *= .25f; }
    *(float4*)(out + (size_t)row * C_ + d) = acc;
}

// ============================================================================
// Kernel 1b: V projection. 32768 threads.
// ============================================================================
__global__ void v_kernel(const float* __restrict__ h, const float* __restrict__ Wv) {
    int gid = blockIdx.x * blockDim.x + threadIdx.x;   // [0, 32768)
    int row = gid >> 5, d = (gid & 31) * 4;
    const float* hrow = h + (size_t)row * C_;
    float4 acc = make_float4(0.f, 0.f, 0.f, 0.f);
#pragma unroll 4
    for (int c = 0; c < C_; c++) {
        float  hv = __ldg(hrow + c);
        float4 w  = *(const float4*)(Wv + (size_t)c * C_ + d);
        acc.x += hv * w.x; acc.y += hv * w.y; acc.z += hv * w.z; acc.w += hv * w.w;
    }
    *(float4*)(g_V + (size_t)row * C_ + d) = acc;
}

// ============================================================================
// Kernel 2 helpers
// ============================================================================
__device__ __forceinline__ void cp_e_tile(uint32_t sb, const float* e,
                                          int bi, int j0, int tid) {
    const float4* esrc = (const float4*)e + ((size_t)bi * N_ + j0) * 32;
#pragma unroll
    for (int it = 0; it < 8; it++) {
        int g = tid + 256 * it;
        CP_ASYNC16(sb + SM_E32 + (uint32_t)g * 16u, (const void*)(esrc + g));
    }
}
// convert fp32 staging -> fp16 swizzled tile at dst
__device__ __forceinline__ void cvt_stage(uint32_t sb, uint32_t dst, int tid) {
#pragma unroll
    for (int it = 0; it < 8; it++) {
        int g = tid + 256 * it;
        int r = g >> 5, c = (g & 31) << 2;
        float4 v;
        LDS128F(v, sb + SM_E32 + (uint32_t)g * 16u);
        __half2 h0 = __float22half2_rn(make_float2(v.x, v.y));
        __half2 h1 = __float22half2_rn(make_float2(v.z, v.w));
        STS64(dst + swz(r, (uint32_t)c * 2u), *(uint32_t*)&h0, *(uint32_t*)&h1);
    }
}

// ============================================================================
// Kernel 2: fp16 mma.sync edge GEMM, stripe-resident K, 1 barrier per tile,
// colsum folded into the epilogue (per-CTA deterministic partials).
// Grid = 288 = 16 stripes (b x j0) x 18 CTAs; CTA iterates i with stride 18.
// ============================================================================
__global__ void __launch_bounds__(256, 2)
edge_kernel(const float* __restrict__ e, float* __restrict__ out_e) {
    extern __shared__ char smem[];
    const uint32_t sb = smem_u32(smem);
    const int tid = threadIdx.x, warp = tid >> 5, lane = tid & 31;
    const int m0 = (warp >> 2) * 32;               // 0 or 32
    const int n0 = (warp & 3) * 32;                // 0..96
    const int stripe = blockIdx.x & 15;            // 16 stripes
    const int w0 = blockIdx.x >> 4;                // 0..17, first i
    const int b = stripe >> 3, j0 = (stripe & 7) << 6;

    // ---- stage W fp16 into SM_E32 (temporarily), swizzled -------------------
#pragma unroll
    for (int it = 0; it < 16; it++) {
        int g = tid + 256 * it;
        int r = g >> 5, c = (g & 31) << 2;
        uint2 a = *(const uint2*)(g_W0T + r * C_ + c);
        STS64(sb + SM_E32 + swz(r, (uint32_t)c * 2u), a.x, a.y);
    }
    __syncthreads();

    // ---- load W fragments into registers (held for the whole kernel) --------
    uint32_t bw[8][2][4];
#pragma unroll
    for (int ks = 0; ks < 8; ks++)
#pragma unroll
        for (int ntp = 0; ntp < 2; ntp++) {
            int drow = n0 + ntp * 16 + ((lane >> 4) << 3) + (lane & 7);
            uint32_t bo = swz(drow, (uint32_t)ks * 32u + (((uint32_t)lane >> 3) & 1u) * 16u);
            LDSM_X4(bw[ks][ntp][0], bw[ks][ntp][1], bw[ks][ntp][2], bw[ks][ntp][3],
                    sb + SM_E32 + bo);
        }
    __syncthreads();

    // ---- prologue: K (once) + e(i=w0); cvt; issue e(w0+18) -------------------
    {
        const float4* ksrc = (const float4*)(g_K + ((size_t)b * N_ + j0) * C_);
#pragma unroll
        for (int it = 0; it < 8; it++) {
            int g = tid + 256 * it;
            int r = g >> 5, m = g & 31;
            CP_ASYNC16(sb + SM_K + (uint32_t)(r * 528 + m * 16), (const void*)(ksrc + g));
        }
    }
    cp_e_tile(sb, e, b * N_ + w0, j0, tid);
    CP_COMMIT();
    CP_WAIT0();
    __syncthreads();                               // K + e(w0) visible CTA-wide
    cvt_stage(sb, SM_E16A + sb, tid);
    if (w0 + STRIDE_I < N_) { cp_e_tile(sb, e, b * N_ + w0 + STRIDE_I, j0, tid); CP_COMMIT(); }
    __syncthreads();                               // E16A visible

    float cs[2][2][2];                             // colsum partials [mt][ntg][r0/r1]
#pragma unroll
    for (int a = 0; a < 2; a++)
#pragma unroll
        for (int bb = 0; bb < 2; bb++) { cs[a][bb][0] = 0.f; cs[a][bb][1] = 0.f; }

    int k = 0;
    for (int i = w0; i < N_; i += STRIDE_I, k++) {
        const int p = k & 1;
        const uint32_t eb = sb + (p ? SM_E16B : SM_E16A);
        const int bi = b * N_ + i;
        const size_t row_base = (size_t)bi * N_ + j0;

        // ---- MMA mainloop (A from eb, W from registers) ---------------------
        float acc[2][4][4];
#pragma unroll
        for (int mt = 0; mt < 2; mt++)
#pragma unroll
            for (int nt = 0; nt < 4; nt++)
#pragma unroll
                for (int kk = 0; kk < 4; kk++) acc[mt][nt][kk] = 0.f;

#pragma unroll
        for (int ks = 0; ks < 8; ks++) {
            uint32_t a0[2][4];
#pragma unroll
            for (int mt = 0; mt < 2; mt++) {
                int arow = m0 + mt * 16 + (lane & 15);
                uint32_t ao = swz(arow, (uint32_t)ks * 32u + ((uint32_t)(lane >> 4)) * 16u);
                LDSM_X4(a0[mt][0], a0[mt][1], a0[mt][2], a0[mt][3], eb + ao);
            }
#pragma unroll
            for (int mt = 0; mt < 2; mt++)
#pragma unroll
                for (int nt = 0; nt < 4; nt++)
                    MMA16816(acc[mt][nt], a0[mt][0], a0[mt][1], a0[mt][2], a0[mt][3],
                             bw[ks][nt >> 1][(nt & 1) * 2], bw[ks][nt >> 1][(nt & 1) * 2 + 1]);
        }

        // ---- epilogue: gate with Q (gmem) and resident K (smem) -------------
        const float* qrow = g_Q + (size_t)bi * C_;
#pragma unroll
        for (int mt = 0; mt < 2; mt++) {
            const int r0 = m0 + mt * 16 + (lane >> 2);   // tile-local j
            const int r1 = r0 + 8;
            float* orow0 = out_e + (row_base + r0) * C_;
            float* orow1 = out_e + (row_base + r1) * C_;
            float hs0 = 0.f, hs1 = 0.f;
#pragma unroll
            for (int nt = 0; nt < 4; nt++) {
                int colp = n0 + nt * 8 + 2 * (lane & 3);
                float2 q2 = *(const float2*)(qrow + colp);
                float2 k0, k1;
                LDS64F(k0, sb + SM_K + (uint32_t)(r0 * 528 + colp * 4));
                LDS64F(k1, sb + SM_K + (uint32_t)(r1 * 528 + colp * 4));
                float2 e0, e1;
                e0.x = acc[mt][nt][0] * q2.x * k0.x;  e0.y = acc[mt][nt][1] * q2.y * k0.y;
                e1.x = acc[mt][nt][2] * q2.x * k1.x;  e1.y = acc[mt][nt][3] * q2.y * k1.y;
                __stcs((float2*)(orow0 + colp), e0);   // streaming: never re-read
                __stcs((float2*)(orow1 + colp), e1);
                hs0 += e0.x + e0.y;
                hs1 += e1.x + e1.y;
                if (nt & 1) {                        // head complete (2 n-tiles)
                    hs0 += __shfl_xor_sync(0xffffffffu, hs0, 1);
                    hs0 += __shfl_xor_sync(0xffffffffu, hs0, 2);
                    hs1 += __shfl_xor_sync(0xffffffffu, hs1, 1);
                    hs1 += __shfl_xor_sync(0xffffffffu, hs1, 2);
                    if ((lane & 3) == 0) {
                        int head = (n0 >> 4) + (nt >> 1);
                        float c0 = __expf(fminf(fmaxf(hs0, -5.f), 5.f));
                        float c1 = __expf(fminf(fmaxf(hs1, -5.f), 5.f));
                        float* sp = g_S + ((size_t)(b * H_ + head) * N_ + i) * N_ + j0;
                        sp[r0] = c0;
                        sp[r1] = c1;
                        cs[mt][nt >> 1][0] += c0;    // fold colsum
                        cs[mt][nt >> 1][1] += c1;
                    }
                    hs0 = 0.f; hs1 = 0.f;
                }
            }
        }

        // ---- cvt e(i+18) into the other fp16 buffer; issue e(i+36) ----------
        if (i + STRIDE_I < N_) {
            CP_WAIT0();
            cvt_stage(sb, sb + (p ? SM_E16A : SM_E16B), tid);
            if (i + 2 * STRIDE_I < N_) {
                cp_e_tile(sb, e, bi + 2 * STRIDE_I, j0, tid);
                CP_COMMIT();
            }
        }
        __syncthreads();   // single barrier: E16[p^1] handoff + tile retire
    }

    // ---- write colsum partials: g_cs2[w0][b*8+head][j0 + r] -----------------
    if ((lane & 3) == 0) {
#pragma unroll
        for (int mt = 0; mt < 2; mt++)
#pragma unroll
            for (int ntg = 0; ntg < 2; ntg++) {
                int head = (n0 >> 4) + ntg;
                int r0 = m0 + mt * 16 + (lane >> 2);
                float* cp = g_cs2 + ((size_t)w0 * 16 + b * H_ + head) * N_ + j0;
                cp[r0]     = cs[mt][ntg][0];
                cp[r0 + 8] = cs[mt][ntg][1];
            }
    }
}

// ============================================================================
// Kernel 3: h_out fused with softmax normalization.
// Transposed pre-scaled V table: sVn[c][j] = sInv[j]*V[j][head*16+c], padded
// row stride 516 -> conflict-free LDS.128 in the inner loop.
// CTA = (bh, i-tile of 16); 256 thr = 16 i x 16 c.
// ============================================================================
__global__ void __launch_bounds__(256)
hout_kernel(float* __restrict__ out_h) {
    __shared__ float sVn[16 * 516];                // ~32.3 KB (c-major, padded)
    __shared__ float sInv[N_];
    int bh = blockIdx.x >> 5, i0 = (blockIdx.x & 31) << 4;
    int b = bh >> 3, head = bh & 7;
    int tid = threadIdx.x;

    for (int tt = 0; tt < 2; tt++) {
        int j = tid + 256 * tt;
        float s = 0.f;
#pragma unroll
        for (int ch = 0; ch < STRIDE_I; ch++)
            s += g_cs2[((size_t)ch * 16 + bh) * N_ + j];
        sInv[j] = 1.f / s;
    }
    __syncthreads();

    for (int it = 0; it < 32; it++) {
        int q = tid + 256 * it;                    // 8192 elements
        int j = q >> 4, c = q & 15;
        sVn[c * 516 + j] = sInv[j] *
            __ldg(g_V + ((size_t)b * N_ + j) * C_ + head * 16 + c);
    }
    __syncthreads();

    int i = i0 + (tid >> 4), c = tid & 15;
    const float4* prow = (const float4*)(g_S + ((size_t)bh * N_ + i) * N_);
    const float4* vrow = (const float4*)(sVn + c * 516);
    float acc = 0.f;
#pragma unroll 8
    for (int j4 = 0; j4 < 128; j4++) {
        float4 p = __ldg(prow + j4);
        float4 v = vrow[j4];
        acc += p.x * v.x + p.y * v.y + p.z * v.z + p.w * v.w;
    }
    out_h[((size_t)b * N_ + i) * C_ + head * 16 + c] = acc;
}

// ============================================================================
extern "C" void kernel_launch(void* const* d_in, const int* in_sizes, int n_in,
                              void* d_out, int out_size) {
    const float* h  = (const float*)d_in[0];
    const float* e  = (const float*)d_in[1];
    const float* Wq = (const float*)d_in[2];
    const float* Wk = (const float*)d_in[3];
    const float* Wv = (const float*)d_in[4];
    const float* We = (const float*)d_in[5];

    float* out_h = (float*)d_out;                      // [B,N,C]
    float* out_e = (float*)d_out + B_ * N_ * C_;       // [B,N,N,C]

    cudaFuncSetAttribute(edge_kernel,
                         cudaFuncAttributeMaxDynamicSharedMemorySize, SM_TOT);

    prep_w_kernel<<<64, 256>>>(We);                    // launch 1
    qk_kernel<<<256, 256>>>(h, Wq, Wk);                // launch 2
    v_kernel<<<128, 256>>>(h, Wv);                     // launch 3
    edge_kernel<<<16 * STRIDE_I, 256, SM_TOT>>>(e, out_e);  // launch 4 (ncu!)
    hout_kernel<<<16 * 32, 256>>>(out_h);              // launch 5
}